// round 9
// baseline (speedup 1.0000x reference)
#include <cuda_runtime.h>
#include <cuda_fp16.h>
#include <cstdint>
#include <cstddef>

#define BATCH 8
#define NH    16
#define DH    64
#define DIM   1024
#define NFR   16
#define NSP   196
#define NTOK  3137            // 1 + 16*196
#define MTOT  (BATCH*NTOK)    // 25096
#define MPAD  (197*128)       // 25216

// ---------------- scratch (device globals; allocation-free) ----------------
__device__ __half g_qkvh[(size_t)MTOT * 3 * DIM];  // fp16 qkv (GEMM1 output)
__device__ __half g_xh[(size_t)MPAD * DIM];        // x in fp16
__device__ __half g_ah[(size_t)MPAD * DIM];        // attention out in fp16
__device__ __half g_w1h[(size_t)3 * DIM * DIM];
__device__ __half g_w2h[(size_t)DIM * DIM];

// ---------------- PTX helpers ----------------
__device__ __forceinline__ uint32_t smem_u32(const void* p) {
    uint32_t a;
    asm("{ .reg .u64 t; cvta.to.shared.u64 t, %1; cvt.u32.u64 %0, t; }" : "=r"(a) : "l"(p));
    return a;
}
__device__ __forceinline__ void cpa16(uint32_t s, const void* g) {
    asm volatile("cp.async.ca.shared.global [%0], [%1], 16;" :: "r"(s), "l"(g) : "memory");
}
__device__ __forceinline__ void cpa_commit() { asm volatile("cp.async.commit_group;" ::: "memory"); }
__device__ __forceinline__ void cpa_wait1()  { asm volatile("cp.async.wait_group 1;" ::: "memory"); }

__device__ __forceinline__ void ldm4(uint32_t* r, uint32_t a) {
    asm volatile("ldmatrix.sync.aligned.m8n8.x4.shared.b16 {%0,%1,%2,%3}, [%4];"
        : "=r"(r[0]), "=r"(r[1]), "=r"(r[2]), "=r"(r[3]) : "r"(a));
}
__device__ __forceinline__ void ldm4t(uint32_t* r, uint32_t a) {
    asm volatile("ldmatrix.sync.aligned.m8n8.x4.trans.shared.b16 {%0,%1,%2,%3}, [%4];"
        : "=r"(r[0]), "=r"(r[1]), "=r"(r[2]), "=r"(r[3]) : "r"(a));
}
__device__ __forceinline__ void mma16816(float* d, const uint32_t* a, const uint32_t* b) {
    asm volatile("mma.sync.aligned.m16n8k16.row.col.f32.f16.f16.f32 "
        "{%0,%1,%2,%3}, {%4,%5,%6,%7}, {%8,%9}, {%0,%1,%2,%3};"
        : "+f"(d[0]), "+f"(d[1]), "+f"(d[2]), "+f"(d[3])
        : "r"(a[0]), "r"(a[1]), "r"(a[2]), "r"(a[3]), "r"(b[0]), "r"(b[1]));
}
__device__ __forceinline__ float ex2f(float x) {
    float y; asm("ex2.approx.f32 %0, %1;" : "=f"(y) : "f"(x)); return y;
}
__device__ __forceinline__ uint32_t packh2(float a, float b) {
    __half2 h = __floats2half2_rn(a, b);
    return *(uint32_t*)&h;
}

// ---------------------------------------------------------------------------
// fp32 -> fp16 convert
// ---------------------------------------------------------------------------
__global__ __launch_bounds__(256) void cvt_h(
    const float* __restrict__ in, __half* __restrict__ out, int n4)
{
    int i = blockIdx.x * blockDim.x + threadIdx.x;
    if (i >= n4) return;
    float4 v = ((const float4*)in)[i];
    ((__half2*)out)[2*i]   = __floats2half2_rn(v.x, v.y);
    ((__half2*)out)[2*i+1] = __floats2half2_rn(v.z, v.w);
}

// ---------------------------------------------------------------------------
// HMMA fp16 GEMM: C[m,n] = sum_k A[m,k]*B[n,k] (+bias if fp32 out).
// 128x128x64 CTA tile, 4 warps of 64x64 (maximal fragment reuse: 8 ldmatrix
// per 32 MMAs), 3-stage cp.async, 2 CTAs/SM. K fixed 1024.
// ---------------------------------------------------------------------------
#define STG_B  32768
#define B_OFF  16384
#define GSMEM  (3 * STG_B)
#define KITERS 16

__device__ __forceinline__ void ld_stage(
    uint32_t dst, const char* A, const char* B, int k0, int tid)
{
    size_t kb = (size_t)k0 * 2;
#pragma unroll
    for (int i = 0; i < 8; ++i) {
        int idx = tid + (i << 7);              // 0..1023
        uint32_t r = idx >> 3, c = idx & 7;    // row 0..127, 16B-chunk 0..7
        uint32_t phys = r * 128 + ((c ^ (r & 7)) << 4);
        size_t go = (size_t)r * 2048 + kb + c * 16;
        cpa16(dst + phys,         A + go);
        cpa16(dst + B_OFF + phys, B + go);
    }
}

template <bool F16OUT>
__global__ __launch_bounds__(128, 2) void gemm_h(
    const __half* __restrict__ Ah, const __half* __restrict__ Bh,
    const float* __restrict__ bias, void* __restrict__ Cv, int M, int N)
{
    extern __shared__ char smem[];
    const uint32_t sb = smem_u32(smem);
    const int tid = threadIdx.x, lane = tid & 31, wid = tid >> 5;
    const int wm = (wid & 1) * 64;
    const int wn = (wid >> 1) * 64;
    const int bm = blockIdx.y * 128, bn = blockIdx.x * 128;

    const char* a0 = (const char*)(Ah + (size_t)bm * 1024);
    const char* b0 = (const char*)(Bh + (size_t)bn * 1024);

    float acc[4][8][4];
#pragma unroll
    for (int i = 0; i < 4; i++)
#pragma unroll
        for (int j = 0; j < 8; j++)
#pragma unroll
            for (int q = 0; q < 4; q++) acc[i][j][q] = 0.f;

    ld_stage(sb,         a0, b0, 0,  tid); cpa_commit();
    ld_stage(sb + STG_B, a0, b0, 64, tid); cpa_commit();

#pragma unroll 1
    for (int it = 0; it < KITERS; ++it) {
        cpa_wait1();
        __syncthreads();
        if (it + 2 < KITERS)
            ld_stage(sb + ((it + 2) % 3) * STG_B, a0, b0, (it + 2) * 64, tid);
        cpa_commit();

        const uint32_t stg = sb + (it % 3) * STG_B;
#pragma unroll
        for (int ks = 0; ks < 4; ++ks) {
            uint32_t ah[4][4];
#pragma unroll
            for (int mt = 0; mt < 4; ++mt) {
                uint32_t row = wm + mt * 16 + (lane & 15);
                uint32_t c = ks * 2 + (lane >> 4);
                ldm4(ah[mt], stg + row * 128 + ((c ^ (row & 7)) << 4));
            }
            uint32_t bh[4][4];
#pragma unroll
            for (int nq = 0; nq < 4; ++nq) {
                uint32_t row = wn + nq * 16 + ((lane >> 4) << 3) + (lane & 7);
                uint32_t c = ks * 2 + ((lane >> 3) & 1);
                ldm4(bh[nq], stg + B_OFF + row * 128 + ((c ^ (row & 7)) << 4));
            }
#pragma unroll
            for (int mt = 0; mt < 4; ++mt)
#pragma unroll
                for (int nq = 0; nq < 4; ++nq)
#pragma unroll
                    for (int h2 = 0; h2 < 2; ++h2)
                        mma16816(acc[mt][nq * 2 + h2], ah[mt], &bh[nq][h2 * 2]);
        }
    }

#pragma unroll
    for (int mt = 0; mt < 4; ++mt) {
        int r0g = bm + wm + mt * 16 + (lane >> 2);
#pragma unroll
        for (int half = 0; half < 2; ++half) {
            int rg = r0g + half * 8;
            if (rg < M) {
                int cbase = bn + wn + (lane & 3) * 2;
                if (F16OUT) {
                    __half* crow = (__half*)Cv + (size_t)rg * N + cbase;
#pragma unroll
                    for (int nt = 0; nt < 8; ++nt)
                        *(__half2*)(crow + nt * 8) = __floats2half2_rn(
                            acc[mt][nt][half * 2 + 0], acc[mt][nt][half * 2 + 1]);
                } else {
                    float* crow = (float*)Cv + (size_t)rg * N + cbase;
#pragma unroll
                    for (int nt = 0; nt < 8; ++nt) {
                        float2 v;
                        v.x = acc[mt][nt][half * 2 + 0] + bias[cbase + nt * 8];
                        v.y = acc[mt][nt][half * 2 + 1] + bias[cbase + nt * 8 + 1];
                        *(float2*)(crow + nt * 8) = v;
                    }
                }
            }
        }
    }
}

// ---------------------------------------------------------------------------
// Fused attention: blocks 0..127 = cls attention (b,h); blocks 128.. =
// spatial attention per (b, h, frame). 224 threads.
// ---------------------------------------------------------------------------
#define QROWS 224
#define KROWS 208
#define QSTR  72
#define SPA_SMEM ((QROWS + 2 * KROWS) * QSTR * 2)   // 92160
#define K2E 0.18033688011112042f                     // 0.125 * log2(e)

__global__ __launch_bounds__(224, 1) void attn_fused(
    const __half* __restrict__ qkv, __half* __restrict__ oh)
{
    extern __shared__ __half smh[];
    const int tid = threadIdx.x, lane = tid & 31, wid = tid >> 5;

    if (blockIdx.x < 128) {
        // ----------------- CLS attention -----------------
        const int bh = blockIdx.x;
        const int b = bh >> 4, h = bh & 15;
        float* s_l   = (float*)smh;            // [7]
        float* s_acc = (float*)smh + 8;        // [7][64]

        const size_t base = (size_t)b * NTOK * 3 * DIM;
        const __half* qp = &qkv[base + h * DH];
        const float q0 = __half2float(qp[lane]) * 0.125f;
        const float q1 = __half2float(qp[lane + 32]) * 0.125f;

        float l = 0.f, a0 = 0.f, a1 = 0.f;
        for (int t = wid; t < NTOK; t += 7) {
            const __half* kp = &qkv[base + (size_t)t * 3 * DIM + DIM + h * DH];
            float s = q0 * __half2float(kp[lane]) + q1 * __half2float(kp[lane + 32]);
#pragma unroll
            for (int off = 16; off > 0; off >>= 1)
                s += __shfl_xor_sync(0xffffffffu, s, off);
            float p = __expf(s);
            const __half* vp = kp + DIM;
            l  += p;
            a0 += p * __half2float(vp[lane]);
            a1 += p * __half2float(vp[lane + 32]);
        }
        s_acc[wid * 64 + lane]      = a0;
        s_acc[wid * 64 + lane + 32] = a1;
        if (lane == 0) s_l[wid] = l;
        __syncthreads();

        if (wid == 0) {
            float L = 0.f, o0 = 0.f, o1 = 0.f;
#pragma unroll
            for (int w = 0; w < 7; w++) {
                L  += s_l[w];
                o0 += s_acc[w * 64 + lane];
                o1 += s_acc[w * 64 + lane + 32];
            }
            float invl = 1.0f / L;
            size_t o = (size_t)b * NTOK * DIM + h * DH;
            oh[o + lane]      = __float2half_rn(o0 * invl);
            oh[o + lane + 32] = __float2half_rn(o1 * invl);
        }
        return;
    }

    // ----------------- spatial attention -----------------
    __half* Qs = smh;
    __half* Ks = smh + QROWS * QSTR;
    __half* Vs = Ks + KROWS * QSTR;

    const int fb  = blockIdx.x - 128;
    const int b   = fb >> 8;
    const int h   = (fb >> 4) & 15;
    const int fr  = fb & 15;
    const size_t tb = (size_t)b * NTOK * 3 * DIM;
    const int f0 = 1 + fr * NSP;

    for (int idx = tid; idx < QROWS * 8; idx += 224) {
        int row = idx >> 3, c = idx & 7;
        uint4 v = make_uint4(0, 0, 0, 0);
        if (row < NSP)
            v = *(const uint4*)&qkv[tb + (size_t)(f0 + row) * 3072 + h * 64 + c * 8];
        *(uint4*)&Qs[row * QSTR + c * 8] = v;
    }
    for (int idx = tid; idx < KROWS * 8; idx += 224) {
        int row = idx >> 3, c = idx & 7;
        uint4 kv = make_uint4(0, 0, 0, 0), vv = make_uint4(0, 0, 0, 0);
        if (row < 197) {
            int gt = (row == 0) ? 0 : (f0 + row - 1);
            const __half* p = &qkv[tb + (size_t)gt * 3072 + 1024 + h * 64 + c * 8];
            kv = *(const uint4*)p;
            vv = *(const uint4*)(p + 1024);
        }
        *(uint4*)&Ks[row * QSTR + c * 8] = kv;
        *(uint4*)&Vs[row * QSTR + c * 8] = vv;
    }
    __syncthreads();

    const uint32_t sQ = smem_u32(Qs), sK = smem_u32(Ks), sV = smem_u32(Vs);
    const int warpM = wid * 32;

    uint32_t qf[2][4][4];
#pragma unroll
    for (int mt = 0; mt < 2; ++mt)
#pragma unroll
        for (int ks = 0; ks < 4; ++ks) {
            uint32_t row = warpM + mt * 16 + (lane & 15);
            uint32_t c = ks * 2 + (lane >> 4);
            ldm4(qf[mt][ks], sQ + row * 144 + c * 16);
        }

    float o[2][8][4];
#pragma unroll
    for (int mt = 0; mt < 2; ++mt)
#pragma unroll
        for (int g = 0; g < 8; ++g)
#pragma unroll
            for (int q = 0; q < 4; ++q) o[mt][g][q] = 0.f;
    float l[2][2] = {{0.f, 0.f}, {0.f, 0.f}};

#pragma unroll 1
    for (int kc = 0; kc < 13; ++kc) {
        uint32_t kf[4][4];
        {
            uint32_t krow = kc * 16 + ((lane >> 4) << 3) + (lane & 7);
#pragma unroll
            for (int ks = 0; ks < 4; ++ks) {
                uint32_t c = ks * 2 + ((lane >> 3) & 1);
                ldm4(kf[ks], sK + krow * 144 + c * 16);
            }
        }
        float s[2][2][4];
#pragma unroll
        for (int mt = 0; mt < 2; ++mt)
#pragma unroll
            for (int h2 = 0; h2 < 2; ++h2)
#pragma unroll
                for (int q = 0; q < 4; ++q) s[mt][h2][q] = 0.f;
#pragma unroll
        for (int mt = 0; mt < 2; ++mt)
#pragma unroll
            for (int ks = 0; ks < 4; ++ks) {
                mma16816(s[mt][0], qf[mt][ks], &kf[ks][0]);
                mma16816(s[mt][1], qf[mt][ks], &kf[ks][2]);
            }
        uint32_t pf[2][4];
#pragma unroll
        for (int mt = 0; mt < 2; ++mt) {
            float p[2][4];
#pragma unroll
            for (int h2 = 0; h2 < 2; ++h2)
#pragma unroll
                for (int q = 0; q < 4; ++q) {
                    int col = kc * 16 + h2 * 8 + (lane & 3) * 2 + (q & 1);
                    float pv = (col < 197) ? ex2f(s[mt][h2][q] * K2E) : 0.f;
                    p[h2][q] = pv;
                    l[mt][q >> 1] += pv;
                }
            pf[mt][0] = packh2(p[0][0], p[0][1]);
            pf[mt][1] = packh2(p[0][2], p[0][3]);
            pf[mt][2] = packh2(p[1][0], p[1][1]);
            pf[mt][3] = packh2(p[1][2], p[1][3]);
        }
        uint32_t vkey = kc * 16 + ((lane >> 3) & 1) * 8 + (lane & 7);
#pragma unroll
        for (int g = 0; g < 4; ++g) {
            uint32_t vf[4];
            uint32_t dimc = g * 16 + (lane >> 4) * 8;
            ldm4t(vf, sV + vkey * 144 + dimc * 2);
            mma16816(o[0][g * 2 + 0], pf[0], &vf[0]);
            mma16816(o[0][g * 2 + 1], pf[0], &vf[2]);
            mma16816(o[1][g * 2 + 0], pf[1], &vf[0]);
            mma16816(o[1][g * 2 + 1], pf[1], &vf[2]);
        }
    }

    float inv[2][2];
#pragma unroll
    for (int mt = 0; mt < 2; ++mt)
#pragma unroll
        for (int rh = 0; rh < 2; ++rh) {
            float ls = l[mt][rh];
            ls += __shfl_xor_sync(0xffffffffu, ls, 1);
            ls += __shfl_xor_sync(0xffffffffu, ls, 2);
            inv[mt][rh] = 1.0f / ls;
        }
#pragma unroll
    for (int mt = 0; mt < 2; ++mt) {
        int row0 = warpM + mt * 16 + (lane >> 2);
#pragma unroll
        for (int rh = 0; rh < 2; ++rh) {
            int row = row0 + rh * 8;
            if (row < NSP) {
                size_t ob = ((size_t)(b * NTOK + f0 + row)) * DIM + h * 64;
                float iv = inv[mt][rh];
#pragma unroll
                for (int g = 0; g < 8; ++g) {
                    int col = g * 8 + (lane & 3) * 2;
                    *(__half2*)&oh[ob + col] = __floats2half2_rn(
                        o[mt][g][rh * 2] * iv, o[mt][g][rh * 2 + 1] * iv);
                }
            }
        }
    }
}

// ---------------------------------------------------------------------------
extern "C" void kernel_launch(void* const* d_in, const int* in_sizes, int n_in,
                              void* d_out, int out_size)
{
    const float* x      = (const float*)d_in[0];
    const float* qkv_w  = (const float*)d_in[1];
    const float* proj_w = (const float*)d_in[2];
    const float* proj_b = (const float*)d_in[3];
    float* out = (float*)d_out;

    __half *qkvh, *xh, *ah, *w1h, *w2h;
    cudaGetSymbolAddress((void**)&qkvh, g_qkvh);
    cudaGetSymbolAddress((void**)&xh,   g_xh);
    cudaGetSymbolAddress((void**)&ah,   g_ah);
    cudaGetSymbolAddress((void**)&w1h,  g_w1h);
    cudaGetSymbolAddress((void**)&w2h,  g_w2h);

    cudaFuncSetAttribute(attn_fused,    cudaFuncAttributeMaxDynamicSharedMemorySize, SPA_SMEM);
    cudaFuncSetAttribute(gemm_h<true>,  cudaFuncAttributeMaxDynamicSharedMemorySize, GSMEM);
    cudaFuncSetAttribute(gemm_h<false>, cudaFuncAttributeMaxDynamicSharedMemorySize, GSMEM);

    // conversions to fp16
    {
        int n4 = MTOT * DIM / 4;
        cvt_h<<<(n4 + 255) / 256, 256>>>(x, xh, n4);
        n4 = 3 * DIM * DIM / 4;
        cvt_h<<<(n4 + 255) / 256, 256>>>(qkv_w, w1h, n4);
        n4 = DIM * DIM / 4;
        cvt_h<<<(n4 + 255) / 256, 256>>>(proj_w, w2h, n4);
    }

    // 1) qkv = x @ qkv_w^T -> fp16 : (25096 x 3072)
    gemm_h<true><<<dim3(3 * DIM / 128, 197), 128, GSMEM>>>(
        xh, w1h, nullptr, qkvh, MTOT, 3 * DIM);

    // 2) attention (cls blocks first, then spatial; fp16 in/out)
    attn_fused<<<128 + BATCH * NH * NFR, 224, SPA_SMEM>>>(qkvh, ah);

    // 3) out = attn @ proj_w^T + proj_b -> fp32 : (25096 x 1024)
    gemm_h<false><<<dim3(DIM / 128, 197), 128, GSMEM>>>(
        ah, w2h, proj_b, out, MTOT, DIM);
}

// round 13
// speedup vs baseline: 1.6226x; 1.6226x over previous
#include <cuda_runtime.h>
#include <cuda_fp16.h>
#include <cstdint>
#include <cstddef>

#define BATCH 8
#define NH    16
#define DH    64
#define DIM   1024
#define NFR   16
#define NSP   196
#define NTOK  3137            // 1 + 16*196
#define MTOT  (BATCH*NTOK)    // 25096
#define MPAD  (197*128)       // 25216

// ---------------- scratch (device globals; allocation-free) ----------------
__device__ __half g_qkvh[(size_t)MTOT * 3 * DIM];  // fp16 qkv (GEMM1 output)
__device__ __half g_xh[(size_t)MPAD * DIM];        // x in fp16
__device__ __half g_ah[(size_t)MPAD * DIM];        // attention out in fp16
__device__ __half g_w1h[(size_t)3 * DIM * DIM];
__device__ __half g_w2h[(size_t)DIM * DIM];

// ---------------- PTX helpers ----------------
__device__ __forceinline__ uint32_t smem_u32(const void* p) {
    uint32_t a;
    asm("{ .reg .u64 t; cvta.to.shared.u64 t, %1; cvt.u32.u64 %0, t; }" : "=r"(a) : "l"(p));
    return a;
}
__device__ __forceinline__ void cpa16(uint32_t s, const void* g) {
    asm volatile("cp.async.cg.shared.global [%0], [%1], 16;" :: "r"(s), "l"(g) : "memory");
}
__device__ __forceinline__ void cpa_commit() { asm volatile("cp.async.commit_group;" ::: "memory"); }
__device__ __forceinline__ void cpa_wait1()  { asm volatile("cp.async.wait_group 1;" ::: "memory"); }

__device__ __forceinline__ void ldm4(uint32_t* r, uint32_t a) {
    asm volatile("ldmatrix.sync.aligned.m8n8.x4.shared.b16 {%0,%1,%2,%3}, [%4];"
        : "=r"(r[0]), "=r"(r[1]), "=r"(r[2]), "=r"(r[3]) : "r"(a));
}
__device__ __forceinline__ void ldm4t(uint32_t* r, uint32_t a) {
    asm volatile("ldmatrix.sync.aligned.m8n8.x4.trans.shared.b16 {%0,%1,%2,%3}, [%4];"
        : "=r"(r[0]), "=r"(r[1]), "=r"(r[2]), "=r"(r[3]) : "r"(a));
}
__device__ __forceinline__ void mma16816(float* d, const uint32_t* a, const uint32_t* b) {
    asm volatile("mma.sync.aligned.m16n8k16.row.col.f32.f16.f16.f32 "
        "{%0,%1,%2,%3}, {%4,%5,%6,%7}, {%8,%9}, {%0,%1,%2,%3};"
        : "+f"(d[0]), "+f"(d[1]), "+f"(d[2]), "+f"(d[3])
        : "r"(a[0]), "r"(a[1]), "r"(a[2]), "r"(a[3]), "r"(b[0]), "r"(b[1]));
}
__device__ __forceinline__ float ex2f(float x) {
    float y; asm("ex2.approx.f32 %0, %1;" : "=f"(y) : "f"(x)); return y;
}
__device__ __forceinline__ uint32_t packh2(float a, float b) {
    __half2 h = __floats2half2_rn(a, b);
    return *(uint32_t*)&h;
}

// ---------------------------------------------------------------------------
// fp32 -> fp16 convert
// ---------------------------------------------------------------------------
__global__ __launch_bounds__(256) void cvt_h(
    const float* __restrict__ in, __half* __restrict__ out, int n4)
{
    int i = blockIdx.x * blockDim.x + threadIdx.x;
    if (i >= n4) return;
    float4 v = ((const float4*)in)[i];
    ((__half2*)out)[2*i]   = __floats2half2_rn(v.x, v.y);
    ((__half2*)out)[2*i+1] = __floats2half2_rn(v.z, v.w);
}

// ---------------------------------------------------------------------------
// HMMA fp16 GEMM: C[m,n] = sum_k A[m,k]*B[n,k] (+bias if fp32 out).
// 128x128x64 CTA tile, 8 warps (4m x 2n) of 32x64, 3-stage cp.async,
// 2 CTAs/SM (16 warps/SM). K fixed 1024.
// ---------------------------------------------------------------------------
#define STG_B  32768
#define B_OFF  16384
#define GSMEM  (3 * STG_B)
#define KITERS 16

__device__ __forceinline__ void ld_stage(
    uint32_t dst, const char* A, const char* B, int k0, int tid)
{
    size_t kb = (size_t)k0 * 2;
#pragma unroll
    for (int i = 0; i < 4; ++i) {
        int idx = tid + (i << 8);
        uint32_t r = idx >> 3, c = idx & 7;
        uint32_t phys = r * 128 + ((c ^ (r & 7)) << 4);
        size_t go = (size_t)r * 2048 + kb + c * 16;
        cpa16(dst + phys,         A + go);
        cpa16(dst + B_OFF + phys, B + go);
    }
}

template <bool F16OUT>
__global__ __launch_bounds__(256, 2) void gemm_h(
    const __half* __restrict__ Ah, const __half* __restrict__ Bh,
    const float* __restrict__ bias, void* __restrict__ Cv, int M, int N)
{
    extern __shared__ char smem[];
    const uint32_t sb = smem_u32(smem);
    const int tid = threadIdx.x, lane = tid & 31, wid = tid >> 5;
    const int wm = (wid & 3) * 32;
    const int wn = (wid >> 2) * 64;
    const int bm = blockIdx.y * 128, bn = blockIdx.x * 128;

    const char* a0 = (const char*)(Ah + (size_t)bm * 1024);
    const char* b0 = (const char*)(Bh + (size_t)bn * 1024);

    float acc[2][8][4];
#pragma unroll
    for (int i = 0; i < 2; i++)
#pragma unroll
        for (int j = 0; j < 8; j++)
#pragma unroll
            for (int q = 0; q < 4; q++) acc[i][j][q] = 0.f;

    ld_stage(sb,         a0, b0, 0,  tid); cpa_commit();
    ld_stage(sb + STG_B, a0, b0, 64, tid); cpa_commit();

#pragma unroll 1
    for (int it = 0; it < KITERS; ++it) {
        cpa_wait1();
        __syncthreads();
        if (it + 2 < KITERS)
            ld_stage(sb + ((it + 2) % 3) * STG_B, a0, b0, (it + 2) * 64, tid);
        cpa_commit();

        const uint32_t stg = sb + (it % 3) * STG_B;
#pragma unroll
        for (int ks = 0; ks < 4; ++ks) {
            uint32_t ah[2][4];
#pragma unroll
            for (int mt = 0; mt < 2; ++mt) {
                uint32_t row = wm + mt * 16 + (lane & 15);
                uint32_t c = ks * 2 + (lane >> 4);
                ldm4(ah[mt], stg + row * 128 + ((c ^ (row & 7)) << 4));
            }
            uint32_t bh[4][4];
#pragma unroll
            for (int nq = 0; nq < 4; ++nq) {
                uint32_t row = wn + nq * 16 + ((lane >> 4) << 3) + (lane & 7);
                uint32_t c = ks * 2 + ((lane >> 3) & 1);
                ldm4(bh[nq], stg + B_OFF + row * 128 + ((c ^ (row & 7)) << 4));
            }
#pragma unroll
            for (int mt = 0; mt < 2; ++mt)
#pragma unroll
                for (int nq = 0; nq < 4; ++nq)
#pragma unroll
                    for (int h2 = 0; h2 < 2; ++h2)
                        mma16816(acc[mt][nq * 2 + h2], ah[mt], &bh[nq][h2 * 2]);
        }
    }

#pragma unroll
    for (int mt = 0; mt < 2; ++mt) {
        int r0g = bm + wm + mt * 16 + (lane >> 2);
#pragma unroll
        for (int half = 0; half < 2; ++half) {
            int rg = r0g + half * 8;
            if (rg < M) {
                int cbase = bn + wn + (lane & 3) * 2;
                if (F16OUT) {
                    __half* crow = (__half*)Cv + (size_t)rg * N + cbase;
#pragma unroll
                    for (int nt = 0; nt < 8; ++nt)
                        *(__half2*)(crow + nt * 8) = __floats2half2_rn(
                            acc[mt][nt][half * 2 + 0], acc[mt][nt][half * 2 + 1]);
                } else {
                    float* crow = (float*)Cv + (size_t)rg * N + cbase;
#pragma unroll
                    for (int nt = 0; nt < 8; ++nt) {
                        float2 v;
                        v.x = acc[mt][nt][half * 2 + 0] + bias[cbase + nt * 8];
                        v.y = acc[mt][nt][half * 2 + 1] + bias[cbase + nt * 8 + 1];
                        *(float2*)(crow + nt * 8) = v;
                    }
                }
            }
        }
    }
}

// ---------------------------------------------------------------------------
// Fused attention: blocks 0..127 = cls attention (b,h); blocks 128.. =
// spatial attention per (b, h, frame). 224 threads.
// ---------------------------------------------------------------------------
#define QROWS 224
#define KROWS 208
#define QSTR  72
#define SPA_SMEM ((QROWS + 2 * KROWS) * QSTR * 2)   // 92160
#define K2E 0.18033688011112042f                     // 0.125 * log2(e)

__global__ __launch_bounds__(224, 1) void attn_fused(
    const __half* __restrict__ qkv, __half* __restrict__ oh)
{
    extern __shared__ __half smh[];
    const int tid = threadIdx.x, lane = tid & 31, wid = tid >> 5;

    if (blockIdx.x < 128) {
        // ----------------- CLS attention -----------------
        const int bh = blockIdx.x;
        const int b = bh >> 4, h = bh & 15;
        float* s_l   = (float*)smh;            // [7]
        float* s_acc = (float*)smh + 8;        // [7][64]

        const size_t base = (size_t)b * NTOK * 3 * DIM;
        const __half* qp = &qkv[base + h * DH];
        const float q0 = __half2float(qp[lane]) * 0.125f;
        const float q1 = __half2float(qp[lane + 32]) * 0.125f;

        float l = 0.f, a0 = 0.f, a1 = 0.f;
        for (int t = wid; t < NTOK; t += 7) {
            const __half* kp = &qkv[base + (size_t)t * 3 * DIM + DIM + h * DH];
            float s = q0 * __half2float(kp[lane]) + q1 * __half2float(kp[lane + 32]);
#pragma unroll
            for (int off = 16; off > 0; off >>= 1)
                s += __shfl_xor_sync(0xffffffffu, s, off);
            float p = __expf(s);
            const __half* vp = kp + DIM;
            l  += p;
            a0 += p * __half2float(vp[lane]);
            a1 += p * __half2float(vp[lane + 32]);
        }
        s_acc[wid * 64 + lane]      = a0;
        s_acc[wid * 64 + lane + 32] = a1;
        if (lane == 0) s_l[wid] = l;
        __syncthreads();

        if (wid == 0) {
            float L = 0.f, o0 = 0.f, o1 = 0.f;
#pragma unroll
            for (int w = 0; w < 7; w++) {
                L  += s_l[w];
                o0 += s_acc[w * 64 + lane];
                o1 += s_acc[w * 64 + lane + 32];
            }
            float invl = 1.0f / L;
            size_t o = (size_t)b * NTOK * DIM + h * DH;
            oh[o + lane]      = __float2half_rn(o0 * invl);
            oh[o + lane + 32] = __float2half_rn(o1 * invl);
        }
        return;
    }

    // ----------------- spatial attention -----------------
    __half* Qs = smh;
    __half* Ks = smh + QROWS * QSTR;
    __half* Vs = Ks + KROWS * QSTR;

    const int fb  = blockIdx.x - 128;
    const int b   = fb >> 8;
    const int h   = (fb >> 4) & 15;
    const int fr  = fb & 15;
    const size_t tb = (size_t)b * NTOK * 3 * DIM;
    const int f0 = 1 + fr * NSP;

    for (int idx = tid; idx < QROWS * 8; idx += 224) {
        int row = idx >> 3, c = idx & 7;
        uint4 v = make_uint4(0, 0, 0, 0);
        if (row < NSP)
            v = *(const uint4*)&qkv[tb + (size_t)(f0 + row) * 3072 + h * 64 + c * 8];
        *(uint4*)&Qs[row * QSTR + c * 8] = v;
    }
    for (int idx = tid; idx < KROWS * 8; idx += 224) {
        int row = idx >> 3, c = idx & 7;
        uint4 kv = make_uint4(0, 0, 0, 0), vv = make_uint4(0, 0, 0, 0);
        if (row < 197) {
            int gt = (row == 0) ? 0 : (f0 + row - 1);
            const __half* p = &qkv[tb + (size_t)gt * 3072 + 1024 + h * 64 + c * 8];
            kv = *(const uint4*)p;
            vv = *(const uint4*)(p + 1024);
        }
        *(uint4*)&Ks[row * QSTR + c * 8] = kv;
        *(uint4*)&Vs[row * QSTR + c * 8] = vv;
    }
    __syncthreads();

    const uint32_t sQ = smem_u32(Qs), sK = smem_u32(Ks), sV = smem_u32(Vs);
    const int warpM = wid * 32;

    uint32_t qf[2][4][4];
#pragma unroll
    for (int mt = 0; mt < 2; ++mt)
#pragma unroll
        for (int ks = 0; ks < 4; ++ks) {
            uint32_t row = warpM + mt * 16 + (lane & 15);
            uint32_t c = ks * 2 + (lane >> 4);
            ldm4(qf[mt][ks], sQ + row * 144 + c * 16);
        }

    float o[2][8][4];
#pragma unroll
    for (int mt = 0; mt < 2; ++mt)
#pragma unroll
        for (int g = 0; g < 8; ++g)
#pragma unroll
            for (int q = 0; q < 4; ++q) o[mt][g][q] = 0.f;
    float l[2][2] = {{0.f, 0.f}, {0.f, 0.f}};

#pragma unroll 1
    for (int kc = 0; kc < 13; ++kc) {
        uint32_t kf[4][4];
        {
            uint32_t krow = kc * 16 + ((lane >> 4) << 3) + (lane & 7);
#pragma unroll
            for (int ks = 0; ks < 4; ++ks) {
                uint32_t c = ks * 2 + ((lane >> 3) & 1);
                ldm4(kf[ks], sK + krow * 144 + c * 16);
            }
        }
        float s[2][2][4];
#pragma unroll
        for (int mt = 0; mt < 2; ++mt)
#pragma unroll
            for (int h2 = 0; h2 < 2; ++h2)
#pragma unroll
                for (int q = 0; q < 4; ++q) s[mt][h2][q] = 0.f;
#pragma unroll
        for (int mt = 0; mt < 2; ++mt)
#pragma unroll
            for (int ks = 0; ks < 4; ++ks) {
                mma16816(s[mt][0], qf[mt][ks], &kf[ks][0]);
                mma16816(s[mt][1], qf[mt][ks], &kf[ks][2]);
            }
        uint32_t pf[2][4];
#pragma unroll
        for (int mt = 0; mt < 2; ++mt) {
            float p[2][4];
#pragma unroll
            for (int h2 = 0; h2 < 2; ++h2)
#pragma unroll
                for (int q = 0; q < 4; ++q) {
                    int col = kc * 16 + h2 * 8 + (lane & 3) * 2 + (q & 1);
                    float pv = (col < 197) ? ex2f(s[mt][h2][q] * K2E) : 0.f;
                    p[h2][q] = pv;
                    l[mt][q >> 1] += pv;
                }
            pf[mt][0] = packh2(p[0][0], p[0][1]);
            pf[mt][1] = packh2(p[0][2], p[0][3]);
            pf[mt][2] = packh2(p[1][0], p[1][1]);
            pf[mt][3] = packh2(p[1][2], p[1][3]);
        }
        uint32_t vkey = kc * 16 + ((lane >> 3) & 1) * 8 + (lane & 7);
#pragma unroll
        for (int g = 0; g < 4; ++g) {
            uint32_t vf[4];
            uint32_t dimc = g * 16 + (lane >> 4) * 8;
            ldm4t(vf, sV + vkey * 144 + dimc * 2);
            mma16816(o[0][g * 2 + 0], pf[0], &vf[0]);
            mma16816(o[0][g * 2 + 1], pf[0], &vf[2]);
            mma16816(o[1][g * 2 + 0], pf[1], &vf[0]);
            mma16816(o[1][g * 2 + 1], pf[1], &vf[2]);
        }
    }

    float inv[2][2];
#pragma unroll
    for (int mt = 0; mt < 2; ++mt)
#pragma unroll
        for (int rh = 0; rh < 2; ++rh) {
            float ls = l[mt][rh];
            ls += __shfl_xor_sync(0xffffffffu, ls, 1);
            ls += __shfl_xor_sync(0xffffffffu, ls, 2);
            inv[mt][rh] = 1.0f / ls;
        }
#pragma unroll
    for (int mt = 0; mt < 2; ++mt) {
        int row0 = warpM + mt * 16 + (lane >> 2);
#pragma unroll
        for (int rh = 0; rh < 2; ++rh) {
            int row = row0 + rh * 8;
            if (row < NSP) {
                size_t ob = ((size_t)(b * NTOK + f0 + row)) * DIM + h * 64;
                float iv = inv[mt][rh];
#pragma unroll
                for (int g = 0; g < 8; ++g) {
                    int col = g * 8 + (lane & 3) * 2;
                    *(__half2*)&oh[ob + col] = __floats2half2_rn(
                        o[mt][g][rh * 2] * iv, o[mt][g][rh * 2 + 1] * iv);
                }
            }
        }
    }
}

// ---------------------------------------------------------------------------
extern "C" void kernel_launch(void* const* d_in, const int* in_sizes, int n_in,
                              void* d_out, int out_size)
{
    const float* x      = (const float*)d_in[0];
    const float* qkv_w  = (const float*)d_in[1];
    const float* proj_w = (const float*)d_in[2];
    const float* proj_b = (const float*)d_in[3];
    float* out = (float*)d_out;

    __half *qkvh, *xh, *ah, *w1h, *w2h;
    cudaGetSymbolAddress((void**)&qkvh, g_qkvh);
    cudaGetSymbolAddress((void**)&xh,   g_xh);
    cudaGetSymbolAddress((void**)&ah,   g_ah);
    cudaGetSymbolAddress((void**)&w1h,  g_w1h);
    cudaGetSymbolAddress((void**)&w2h,  g_w2h);

    cudaFuncSetAttribute(attn_fused,    cudaFuncAttributeMaxDynamicSharedMemorySize, SPA_SMEM);
    cudaFuncSetAttribute(gemm_h<true>,  cudaFuncAttributeMaxDynamicSharedMemorySize, GSMEM);
    cudaFuncSetAttribute(gemm_h<false>, cudaFuncAttributeMaxDynamicSharedMemorySize, GSMEM);

    // conversions to fp16
    {
        int n4 = MTOT * DIM / 4;
        cvt_h<<<(n4 + 255) / 256, 256>>>(x, xh, n4);
        n4 = 3 * DIM * DIM / 4;
        cvt_h<<<(n4 + 255) / 256, 256>>>(qkv_w, w1h, n4);
        n4 = DIM * DIM / 4;
        cvt_h<<<(n4 + 255) / 256, 256>>>(proj_w, w2h, n4);
    }

    // 1) qkv = x @ qkv_w^T -> fp16 : (25096 x 3072)
    gemm_h<true><<<dim3(3 * DIM / 128, 197), 256, GSMEM>>>(
        xh, w1h, nullptr, qkvh, MTOT, 3 * DIM);

    // 2) attention (cls blocks first, then spatial; fp16 in/out)
    attn_fused<<<128 + BATCH * NH * NFR, 224, SPA_SMEM>>>(qkvh, ah);

    // 3) out = attn @ proj_w^T + proj_b -> fp32 : (25096 x 1024)
    gemm_h<false><<<dim3(DIM / 128, 197), 256, GSMEM>>>(
        ah, w2h, proj_b, out, MTOT, DIM);
}

// round 15
// speedup vs baseline: 1.8928x; 1.1665x over previous
#include <cuda_runtime.h>
#include <cuda_fp16.h>
#include <cstdint>
#include <cstddef>

#define BATCH 8
#define NH    16
#define DH    64
#define DIM   1024
#define NFR   16
#define NSP   196
#define NTOK  3137            // 1 + 16*196
#define MTOT  (BATCH*NTOK)    // 25096
#define MPAD  (197*128)       // 25216

// ---------------- scratch (device globals; allocation-free) ----------------
__device__ __half g_qkvh[(size_t)MTOT * 3 * DIM];  // fp16 qkv (GEMM1 output)
__device__ __half g_xh[(size_t)MPAD * DIM];        // x in fp16
__device__ __half g_ah[(size_t)MPAD * DIM];        // attention out in fp16
__device__ __half g_w1h[(size_t)3 * DIM * DIM];
__device__ __half g_w2h[(size_t)DIM * DIM];

// ---------------- PTX helpers ----------------
__device__ __forceinline__ uint32_t smem_u32(const void* p) {
    uint32_t a;
    asm("{ .reg .u64 t; cvta.to.shared.u64 t, %1; cvt.u32.u64 %0, t; }" : "=r"(a) : "l"(p));
    return a;
}
__device__ __forceinline__ void cpa16(uint32_t s, const void* g) {
    asm volatile("cp.async.cg.shared.global [%0], [%1], 16;" :: "r"(s), "l"(g) : "memory");
}
__device__ __forceinline__ void cpa_commit() { asm volatile("cp.async.commit_group;" ::: "memory"); }
__device__ __forceinline__ void cpa_wait1()  { asm volatile("cp.async.wait_group 1;" ::: "memory"); }

__device__ __forceinline__ void ldm4(uint32_t* r, uint32_t a) {
    asm volatile("ldmatrix.sync.aligned.m8n8.x4.shared.b16 {%0,%1,%2,%3}, [%4];"
        : "=r"(r[0]), "=r"(r[1]), "=r"(r[2]), "=r"(r[3]) : "r"(a));
}
__device__ __forceinline__ void ldm4t(uint32_t* r, uint32_t a) {
    asm volatile("ldmatrix.sync.aligned.m8n8.x4.trans.shared.b16 {%0,%1,%2,%3}, [%4];"
        : "=r"(r[0]), "=r"(r[1]), "=r"(r[2]), "=r"(r[3]) : "r"(a));
}
__device__ __forceinline__ void mma16816(float* d, const uint32_t* a, const uint32_t* b) {
    asm volatile("mma.sync.aligned.m16n8k16.row.col.f32.f16.f16.f32 "
        "{%0,%1,%2,%3}, {%4,%5,%6,%7}, {%8,%9}, {%0,%1,%2,%3};"
        : "+f"(d[0]), "+f"(d[1]), "+f"(d[2]), "+f"(d[3])
        : "r"(a[0]), "r"(a[1]), "r"(a[2]), "r"(a[3]), "r"(b[0]), "r"(b[1]));
}
__device__ __forceinline__ float ex2f(float x) {
    float y; asm("ex2.approx.f32 %0, %1;" : "=f"(y) : "f"(x)); return y;
}
__device__ __forceinline__ uint32_t packh2(float a, float b) {
    __half2 h = __floats2half2_rn(a, b);
    return *(uint32_t*)&h;
}

// ---------------------------------------------------------------------------
// fp32 -> fp16 convert
// ---------------------------------------------------------------------------
__global__ __launch_bounds__(256) void cvt_h(
    const float* __restrict__ in, __half* __restrict__ out, int n4)
{
    int i = blockIdx.x * blockDim.x + threadIdx.x;
    if (i >= n4) return;
    float4 v = ((const float4*)in)[i];
    ((__half2*)out)[2*i]   = __floats2half2_rn(v.x, v.y);
    ((__half2*)out)[2*i+1] = __floats2half2_rn(v.z, v.w);
}

// ---------------------------------------------------------------------------
// HMMA fp16 GEMM: C[m,n] = sum_k A[m,k]*B[n,k] (+bias if fp32 out).
// 128x128x64 CTA tile, 8 warps (4m x 2n) of 32x64, 3-stage cp.async,
// 2 CTAs/SM (16 warps/SM). K fixed 1024.
// ---------------------------------------------------------------------------
#define STG_B  32768
#define B_OFF  16384
#define GSMEM  (3 * STG_B)
#define KITERS 16

__device__ __forceinline__ void ld_stage(
    uint32_t dst, const char* A, const char* B, int k0, int tid)
{
    size_t kb = (size_t)k0 * 2;
#pragma unroll
    for (int i = 0; i < 4; ++i) {
        int idx = tid + (i << 8);
        uint32_t r = idx >> 3, c = idx & 7;
        uint32_t phys = r * 128 + ((c ^ (r & 7)) << 4);
        size_t go = (size_t)r * 2048 + kb + c * 16;
        cpa16(dst + phys,         A + go);
        cpa16(dst + B_OFF + phys, B + go);
    }
}

template <bool F16OUT>
__global__ __launch_bounds__(256, 2) void gemm_h(
    const __half* __restrict__ Ah, const __half* __restrict__ Bh,
    const float* __restrict__ bias, void* __restrict__ Cv, int M, int N)
{
    extern __shared__ char smem[];
    const uint32_t sb = smem_u32(smem);
    const int tid = threadIdx.x, lane = tid & 31, wid = tid >> 5;
    const int wm = (wid & 3) * 32;
    const int wn = (wid >> 2) * 64;
    const int bm = blockIdx.y * 128, bn = blockIdx.x * 128;

    const char* a0 = (const char*)(Ah + (size_t)bm * 1024);
    const char* b0 = (const char*)(Bh + (size_t)bn * 1024);

    float acc[2][8][4];
#pragma unroll
    for (int i = 0; i < 2; i++)
#pragma unroll
        for (int j = 0; j < 8; j++)
#pragma unroll
            for (int q = 0; q < 4; q++) acc[i][j][q] = 0.f;

    ld_stage(sb,         a0, b0, 0,  tid); cpa_commit();
    ld_stage(sb + STG_B, a0, b0, 64, tid); cpa_commit();

#pragma unroll 1
    for (int it = 0; it < KITERS; ++it) {
        cpa_wait1();
        __syncthreads();
        if (it + 2 < KITERS)
            ld_stage(sb + ((it + 2) % 3) * STG_B, a0, b0, (it + 2) * 64, tid);
        cpa_commit();

        const uint32_t stg = sb + (it % 3) * STG_B;
#pragma unroll
        for (int ks = 0; ks < 4; ++ks) {
            uint32_t ah[2][4];
#pragma unroll
            for (int mt = 0; mt < 2; ++mt) {
                uint32_t row = wm + mt * 16 + (lane & 15);
                uint32_t c = ks * 2 + (lane >> 4);
                ldm4(ah[mt], stg + row * 128 + ((c ^ (row & 7)) << 4));
            }
            uint32_t bh[4][4];
#pragma unroll
            for (int nq = 0; nq < 4; ++nq) {
                uint32_t row = wn + nq * 16 + ((lane >> 4) << 3) + (lane & 7);
                uint32_t c = ks * 2 + ((lane >> 3) & 1);
                ldm4(bh[nq], stg + B_OFF + row * 128 + ((c ^ (row & 7)) << 4));
            }
#pragma unroll
            for (int mt = 0; mt < 2; ++mt)
#pragma unroll
                for (int nq = 0; nq < 4; ++nq)
#pragma unroll
                    for (int h2 = 0; h2 < 2; ++h2)
                        mma16816(acc[mt][nq * 2 + h2], ah[mt], &bh[nq][h2 * 2]);
        }
    }

#pragma unroll
    for (int mt = 0; mt < 2; ++mt) {
        int r0g = bm + wm + mt * 16 + (lane >> 2);
#pragma unroll
        for (int half = 0; half < 2; ++half) {
            int rg = r0g + half * 8;
            if (rg < M) {
                int cbase = bn + wn + (lane & 3) * 2;
                if (F16OUT) {
                    __half* crow = (__half*)Cv + (size_t)rg * N + cbase;
#pragma unroll
                    for (int nt = 0; nt < 8; ++nt)
                        *(__half2*)(crow + nt * 8) = __floats2half2_rn(
                            acc[mt][nt][half * 2 + 0], acc[mt][nt][half * 2 + 1]);
                } else {
                    float* crow = (float*)Cv + (size_t)rg * N + cbase;
#pragma unroll
                    for (int nt = 0; nt < 8; ++nt) {
                        float2 v;
                        v.x = acc[mt][nt][half * 2 + 0] + bias[cbase + nt * 8];
                        v.y = acc[mt][nt][half * 2 + 1] + bias[cbase + nt * 8 + 1];
                        *(float2*)(crow + nt * 8) = v;
                    }
                }
            }
        }
    }
}

// ---------------------------------------------------------------------------
// Fused attention: blocks 0..127 = cls attention (b,h); blocks 128.. =
// spatial attention per (b, h, frame). 224 threads, 2 CTAs/SM.
// Smem reused: Q staged first (fragments -> regs), then K/V overwrite it.
// ---------------------------------------------------------------------------
#define QROWS 224
#define KROWS 208
#define QSTR  72
#define SPA_SMEM (2 * KROWS * QSTR * 2)             // 59904
#define K2E 0.18033688011112042f                     // 0.125 * log2(e)

__global__ __launch_bounds__(224, 2) void attn_fused(
    const __half* __restrict__ qkv, __half* __restrict__ oh)
{
    extern __shared__ __half smh[];
    const int tid = threadIdx.x, lane = tid & 31, wid = tid >> 5;

    if (blockIdx.x < 128) {
        // ----------------- CLS attention -----------------
        const int bh = blockIdx.x;
        const int b = bh >> 4, h = bh & 15;
        float* s_l   = (float*)smh;            // [7]
        float* s_acc = (float*)smh + 8;        // [7][64]

        const size_t base = (size_t)b * NTOK * 3 * DIM;
        const __half* qp = &qkv[base + h * DH];
        const float q0 = __half2float(qp[lane]) * 0.125f;
        const float q1 = __half2float(qp[lane + 32]) * 0.125f;

        float l = 0.f, a0 = 0.f, a1 = 0.f;
        for (int t = wid; t < NTOK; t += 7) {
            const __half* kp = &qkv[base + (size_t)t * 3 * DIM + DIM + h * DH];
            float s = q0 * __half2float(kp[lane]) + q1 * __half2float(kp[lane + 32]);
#pragma unroll
            for (int off = 16; off > 0; off >>= 1)
                s += __shfl_xor_sync(0xffffffffu, s, off);
            float p = __expf(s);
            const __half* vp = kp + DIM;
            l  += p;
            a0 += p * __half2float(vp[lane]);
            a1 += p * __half2float(vp[lane + 32]);
        }
        s_acc[wid * 64 + lane]      = a0;
        s_acc[wid * 64 + lane + 32] = a1;
        if (lane == 0) s_l[wid] = l;
        __syncthreads();

        if (wid == 0) {
            float L = 0.f, o0 = 0.f, o1 = 0.f;
#pragma unroll
            for (int w = 0; w < 7; w++) {
                L  += s_l[w];
                o0 += s_acc[w * 64 + lane];
                o1 += s_acc[w * 64 + lane + 32];
            }
            float invl = 1.0f / L;
            size_t o = (size_t)b * NTOK * DIM + h * DH;
            oh[o + lane]      = __float2half_rn(o0 * invl);
            oh[o + lane + 32] = __float2half_rn(o1 * invl);
        }
        return;
    }

    // ----------------- spatial attention -----------------
    __half* Ks = smh;                   // 208*72 (also used as Q staging)
    __half* Vs = smh + KROWS * QSTR;    // 208*72

    const int fb  = blockIdx.x - 128;
    const int b   = fb >> 8;
    const int h   = (fb >> 4) & 15;
    const int fr  = fb & 15;
    const size_t tb = (size_t)b * NTOK * 3 * DIM;
    const int f0 = 1 + fr * NSP;

    // --- Phase 1: stage Q (224 rows; rows >=196 zeroed), read fragments ---
    for (int idx = tid; idx < QROWS * 8; idx += 224) {
        int row = idx >> 3, c = idx & 7;
        uint4 v = make_uint4(0, 0, 0, 0);
        if (row < NSP)
            v = *(const uint4*)&qkv[tb + (size_t)(f0 + row) * 3072 + h * 64 + c * 8];
        // rows 0..207 in Ks area, rows 208..223 spill into Vs area (contiguous)
        *(uint4*)&smh[row * QSTR + c * 8] = v;
    }
    __syncthreads();

    const uint32_t sQ = smem_u32(smh);
    const int warpM = wid * 32;

    uint32_t qf[2][4][4];
#pragma unroll
    for (int mt = 0; mt < 2; ++mt)
#pragma unroll
        for (int ks = 0; ks < 4; ++ks) {
            uint32_t row = warpM + mt * 16 + (lane & 15);
            uint32_t c = ks * 2 + (lane >> 4);
            ldm4(qf[mt][ks], sQ + row * 144 + c * 16);
        }
    __syncthreads();

    // --- Phase 2: stage K and V (208 rows; row0 = cls, rows >=197 zeroed) ---
    for (int idx = tid; idx < KROWS * 8; idx += 224) {
        int row = idx >> 3, c = idx & 7;
        uint4 kv = make_uint4(0, 0, 0, 0), vv = make_uint4(0, 0, 0, 0);
        if (row < 197) {
            int gt = (row == 0) ? 0 : (f0 + row - 1);
            const __half* p = &qkv[tb + (size_t)gt * 3072 + 1024 + h * 64 + c * 8];
            kv = *(const uint4*)p;
            vv = *(const uint4*)(p + 1024);
        }
        *(uint4*)&Ks[row * QSTR + c * 8] = kv;
        *(uint4*)&Vs[row * QSTR + c * 8] = vv;
    }
    __syncthreads();

    const uint32_t sK = smem_u32(Ks), sV = smem_u32(Vs);

    float o[2][8][4];
#pragma unroll
    for (int mt = 0; mt < 2; ++mt)
#pragma unroll
        for (int g = 0; g < 8; ++g)
#pragma unroll
            for (int q = 0; q < 4; ++q) o[mt][g][q] = 0.f;
    float l[2][2] = {{0.f, 0.f}, {0.f, 0.f}};

#pragma unroll 1
    for (int kc = 0; kc < 13; ++kc) {
        uint32_t kf[4][4];
        {
            uint32_t krow = kc * 16 + ((lane >> 4) << 3) + (lane & 7);
#pragma unroll
            for (int ks = 0; ks < 4; ++ks) {
                uint32_t c = ks * 2 + ((lane >> 3) & 1);
                ldm4(kf[ks], sK + krow * 144 + c * 16);
            }
        }
        float s[2][2][4];
#pragma unroll
        for (int mt = 0; mt < 2; ++mt)
#pragma unroll
            for (int h2 = 0; h2 < 2; ++h2)
#pragma unroll
                for (int q = 0; q < 4; ++q) s[mt][h2][q] = 0.f;
#pragma unroll
        for (int mt = 0; mt < 2; ++mt)
#pragma unroll
            for (int ks = 0; ks < 4; ++ks) {
                mma16816(s[mt][0], qf[mt][ks], &kf[ks][0]);
                mma16816(s[mt][1], qf[mt][ks], &kf[ks][2]);
            }
        uint32_t pf[2][4];
#pragma unroll
        for (int mt = 0; mt < 2; ++mt) {
            float p[2][4];
#pragma unroll
            for (int h2 = 0; h2 < 2; ++h2)
#pragma unroll
                for (int q = 0; q < 4; ++q) {
                    int col = kc * 16 + h2 * 8 + (lane & 3) * 2 + (q & 1);
                    float pv = (col < 197) ? ex2f(s[mt][h2][q] * K2E) : 0.f;
                    p[h2][q] = pv;
                    l[mt][q >> 1] += pv;
                }
            pf[mt][0] = packh2(p[0][0], p[0][1]);
            pf[mt][1] = packh2(p[0][2], p[0][3]);
            pf[mt][2] = packh2(p[1][0], p[1][1]);
            pf[mt][3] = packh2(p[1][2], p[1][3]);
        }
        uint32_t vkey = kc * 16 + ((lane >> 3) & 1) * 8 + (lane & 7);
#pragma unroll
        for (int g = 0; g < 4; ++g) {
            uint32_t vf[4];
            uint32_t dimc = g * 16 + (lane >> 4) * 8;
            ldm4t(vf, sV + vkey * 144 + dimc * 2);
            mma16816(o[0][g * 2 + 0], pf[0], &vf[0]);
            mma16816(o[0][g * 2 + 1], pf[0], &vf[2]);
            mma16816(o[1][g * 2 + 0], pf[1], &vf[0]);
            mma16816(o[1][g * 2 + 1], pf[1], &vf[2]);
        }
    }

    float inv[2][2];
#pragma unroll
    for (int mt = 0; mt < 2; ++mt)
#pragma unroll
        for (int rh = 0; rh < 2; ++rh) {
            float ls = l[mt][rh];
            ls += __shfl_xor_sync(0xffffffffu, ls, 1);
            ls += __shfl_xor_sync(0xffffffffu, ls, 2);
            inv[mt][rh] = 1.0f / ls;
        }
#pragma unroll
    for (int mt = 0; mt < 2; ++mt) {
        int row0 = warpM + mt * 16 + (lane >> 2);
#pragma unroll
        for (int rh = 0; rh < 2; ++rh) {
            int row = row0 + rh * 8;
            if (row < NSP) {
                size_t ob = ((size_t)(b * NTOK + f0 + row)) * DIM + h * 64;
                float iv = inv[mt][rh];
#pragma unroll
                for (int g = 0; g < 8; ++g) {
                    int col = g * 8 + (lane & 3) * 2;
                    *(__half2*)&oh[ob + col] = __floats2half2_rn(
                        o[mt][g][rh * 2] * iv, o[mt][g][rh * 2 + 1] * iv);
                }
            }
        }
    }
}

// ---------------------------------------------------------------------------
extern "C" void kernel_launch(void* const* d_in, const int* in_sizes, int n_in,
                              void* d_out, int out_size)
{
    const float* x      = (const float*)d_in[0];
    const float* qkv_w  = (const float*)d_in[1];
    const float* proj_w = (const float*)d_in[2];
    const float* proj_b = (const float*)d_in[3];
    float* out = (float*)d_out;

    __half *qkvh, *xh, *ah, *w1h, *w2h;
    cudaGetSymbolAddress((void**)&qkvh, g_qkvh);
    cudaGetSymbolAddress((void**)&xh,   g_xh);
    cudaGetSymbolAddress((void**)&ah,   g_ah);
    cudaGetSymbolAddress((void**)&w1h,  g_w1h);
    cudaGetSymbolAddress((void**)&w2h,  g_w2h);

    cudaFuncSetAttribute(attn_fused,    cudaFuncAttributeMaxDynamicSharedMemorySize, SPA_SMEM);
    cudaFuncSetAttribute(gemm_h<true>,  cudaFuncAttributeMaxDynamicSharedMemorySize, GSMEM);
    cudaFuncSetAttribute(gemm_h<false>, cudaFuncAttributeMaxDynamicSharedMemorySize, GSMEM);

    // conversions to fp16
    {
        int n4 = MTOT * DIM / 4;
        cvt_h<<<(n4 + 255) / 256, 256>>>(x, xh, n4);
        n4 = 3 * DIM * DIM / 4;
        cvt_h<<<(n4 + 255) / 256, 256>>>(qkv_w, w1h, n4);
        n4 = DIM * DIM / 4;
        cvt_h<<<(n4 + 255) / 256, 256>>>(proj_w, w2h, n4);
    }

    // 1) qkv = x @ qkv_w^T -> fp16 : (25096 x 3072)
    gemm_h<true><<<dim3(3 * DIM / 128, 197), 256, GSMEM>>>(
        xh, w1h, nullptr, qkvh, MTOT, 3 * DIM);

    // 2) attention (cls blocks first, then spatial; fp16 in/out)
    attn_fused<<<128 + BATCH * NH * NFR, 224, SPA_SMEM>>>(qkvh, ah);

    // 3) out = attn @ proj_w^T + proj_b -> fp32 : (25096 x 1024)
    gemm_h<false><<<dim3(DIM / 128, 197), 256, GSMEM>>>(
        ah, w2h, proj_b, out, MTOT, DIM);
}